// round 10
// baseline (speedup 1.0000x reference)
#include <cuda_runtime.h>
#include <cuda_bf16.h>
#include <stdint.h>
#include <math.h>

// ---------------- problem constants ----------------
#define BB   16
#define SS_  512
#define DD   768
#define EE   128
#define RR   2048
#define HH   768
#define HH2  384
#define ME   (BB * EE)        // 2048 entity rows
#define NREL (BB * RR)        // 32768 relations
#define RELBLOCKS (NREL / 8)
#define N1   (2 * HH)         // 1536 (head|tail fused layer1 output)

// ---------------- scratch (static device globals) ----------------
__device__ __nv_bfloat16 g_repH[ME * DD],  g_repL[ME * DD];
__device__ __nv_bfloat16 g_w1H [N1 * DD],  g_w1L [N1 * DD];
__device__ __nv_bfloat16 g_h1H [ME * N1],  g_h1L [ME * N1];
__device__ __nv_bfloat16 g_w2hH[HH2 * HH], g_w2hL[HH2 * HH];
__device__ __nv_bfloat16 g_w2tH[HH2 * HH], g_w2tL[HH2 * HH];
__device__ __nv_bfloat16 g_eHH [ME * HH2], g_eHL [ME * HH2];
__device__ __nv_bfloat16 g_bilH[2 * HH2 * HH2], g_bilL[2 * HH2 * HH2];
__device__ float g_embW1[3 * N1];
__device__ float g_eH[ME * HH2], g_eT[ME * HH2];
__device__ float g_hb[ME * 2 * HH2];
__device__ float g_hlin[ME * 2], g_tlin[ME * 2];
__device__ float g_partials[RELBLOCKS];

// ---------------- helpers ----------------
__device__ __forceinline__ uint32_t smem_u32(const void* p) {
    uint32_t a;
    asm("{ .reg .u64 t; cvta.to.shared.u64 t, %1; cvt.u32.u64 %0, t; }" : "=r"(a) : "l"(p));
    return a;
}
__device__ __forceinline__ void cpa16(uint32_t dst, const void* src) {
    asm volatile("cp.async.cg.shared.global [%0], [%1], 16;" :: "r"(dst), "l"(src));
}
#define CP_COMMIT() asm volatile("cp.async.commit_group;" ::: "memory")

#define LDSM4(r, addr) \
    asm volatile("ldmatrix.sync.aligned.m8n8.x4.shared.b16 {%0,%1,%2,%3}, [%4];" \
        : "=r"((r)[0]), "=r"((r)[1]), "=r"((r)[2]), "=r"((r)[3]) : "r"(addr))

#define MMA16816(d, a, b) \
    asm volatile("mma.sync.aligned.m16n8k16.row.col.f32.bf16.bf16.f32 " \
        "{%0,%1,%2,%3}, {%4,%5,%6,%7}, {%8,%9}, {%0,%1,%2,%3};" \
        : "+f"((d)[0]), "+f"((d)[1]), "+f"((d)[2]), "+f"((d)[3]) \
        : "r"((a)[0]), "r"((a)[1]), "r"((a)[2]), "r"((a)[3]), "r"((b)[0]), "r"((b)[1]))

__device__ __forceinline__ void split2(float x, __nv_bfloat16& h, __nv_bfloat16& l) {
    h = __float2bfloat16(x);
    l = __float2bfloat16(x - __bfloat162float(h));
}

// ---------------- gather + convert (hid part only) ----------------
__global__ void gather_kernel(const float* __restrict__ hs,
                              const int* __restrict__ es) {
    int m = blockIdx.x;
    int b = m >> 7;
    int s = es[m];
    const float* src = hs + ((size_t)b * SS_ + s) * DD;
    size_t rb = (size_t)m * DD;
    for (int i = threadIdx.x; i < DD; i += 256) {
        __nv_bfloat16 h, l;
        split2(src[i], h, l);
        g_repH[rb + i] = h; g_repL[rb + i] = l;
    }
}

// ---------------- embW1[l, n] = emb[l] @ W1_bottom[:, n] + b1[n]  (exact fp32) ----------------
__global__ void embw1_kernel(const float* __restrict__ emb,
                             const float* __restrict__ hW1, const float* __restrict__ hb1,
                             const float* __restrict__ tW1, const float* __restrict__ tb1) {
    int o = blockIdx.x * 8 + (threadIdx.x >> 5);
    int lane = threadIdx.x & 31;
    int l = o / N1, n = o % N1;
    const float* er = emb + (size_t)l * DD;
    const float* w;
    float bias;
    if (n < HH) { w = hW1 + (size_t)DD * HH + n;        bias = hb1[n]; }
    else        { w = tW1 + (size_t)DD * HH + (n - HH); bias = tb1[n - HH]; }
    float a = 0.f;
    for (int k = lane; k < DD; k += 32) a = fmaf(er[k], w[(size_t)k * HH], a);
#pragma unroll
    for (int off = 16; off; off >>= 1) a += __shfl_xor_sync(0xffffffffu, a, off);
    if (lane == 0) g_embW1[o] = a + bias;
}

// ---------------- all weight transposes+converts in ONE launch ----------------
__global__ void wconv_all(const float* __restrict__ hW1, const float* __restrict__ tW1,
                          const float* __restrict__ hW2, const float* __restrict__ tW2,
                          const float* __restrict__ bil) {
    __shared__ float t[32][33];
    int id = blockIdx.x;
    const float* W; int K, N; __nv_bfloat16 *oH, *oL;
    if (id < 576)       { W = hW1;             K = 768; N = 768; oH = g_w1H;             oL = g_w1L; }
    else if (id < 1152) { W = tW1;             K = 768; N = 768; oH = g_w1H + 768 * 768; oL = g_w1L + 768 * 768; id -= 576; }
    else if (id < 1440) { W = hW2;             K = 768; N = 384; oH = g_w2hH;            oL = g_w2hL; id -= 1152; }
    else if (id < 1728) { W = tW2;             K = 768; N = 384; oH = g_w2tH;            oL = g_w2tL; id -= 1440; }
    else if (id < 1872) { W = bil;             K = 384; N = 384; oH = g_bilH;            oL = g_bilL; id -= 1728; }
    else                { W = bil + 384 * 384; K = 384; N = 384; oH = g_bilH + 384 * 384; oL = g_bilL + 384 * 384; id -= 1872; }
    int ntiles = N / 32;
    int n0 = (id % ntiles) * 32, k0 = (id / ntiles) * 32;
    int tx = threadIdx.x, ty = threadIdx.y;
#pragma unroll
    for (int j = 0; j < 32; j += 8)
        t[ty + j][tx] = W[(size_t)(k0 + ty + j) * N + n0 + tx];
    __syncthreads();
#pragma unroll
    for (int j = 0; j < 32; j += 8) {
        int n = n0 + ty + j, k = k0 + tx;
        __nv_bfloat16 h, l;
        split2(t[tx][ty + j], h, l);
        oH[(size_t)n * K + k] = h;
        oL[(size_t)n * K + k] = l;
    }
}

// ---------------- mma.sync split-bf16 GEMM, multi-stage cp.async pipeline ----------------
struct GJob {
    const __nv_bfloat16 *aH, *aL; int lda;
    const __nv_bfloat16 *bH, *bL;            // ldb = K
    const float* bias;
    const float* rowTab; const int* rowLab; int ldTab;
    __nv_bfloat16 *outH, *outL;
    float* outF;
    int ldo;
    int relu;
};

template <int BM>
__device__ __forceinline__ void load_stage(uint32_t sbase, const GJob& j,
                                           int m0, int n0, int k0, int tid, int K) {
    const int ACH = BM * 4;                  // 16B chunks per A matrix
#pragma unroll
    for (int idx = tid; idx < 2 * ACH + 1024; idx += 256) {
        if (idx < ACH) {
            int row = idx >> 2, ch = idx & 3;
            cpa16(sbase + row * 80 + ch * 16, j.aH + (size_t)(m0 + row) * j.lda + k0 + ch * 8);
        } else if (idx < 2 * ACH) {
            int q = idx - ACH; int row = q >> 2, ch = q & 3;
            cpa16(sbase + BM * 80 + row * 80 + ch * 16, j.aL + (size_t)(m0 + row) * j.lda + k0 + ch * 8);
        } else if (idx < 2 * ACH + 512) {
            int q = idx - 2 * ACH; int row = q >> 2, ch = q & 3;
            cpa16(sbase + 2 * BM * 80 + row * 80 + ch * 16, j.bH + (size_t)(n0 + row) * K + k0 + ch * 8);
        } else {
            int q = idx - 2 * ACH - 512; int row = q >> 2, ch = q & 3;
            cpa16(sbase + 2 * BM * 80 + 10240 + row * 80 + ch * 16, j.bL + (size_t)(n0 + row) * K + k0 + ch * 8);
        }
    }
}

template <int BM, int STAGES, int MINB>
__global__ void __launch_bounds__(256, MINB)
mma_gemm(GJob j0, GJob j1, int splitX, int K) {
    constexpr int MT = BM / 32;
    constexpr int MAT_A = BM * 80;
    constexpr int OFF_B = 2 * BM * 80;
    constexpr int STAGE = 2 * BM * 80 + 20480;
    extern __shared__ char smem[];
    const uint32_t sb = smem_u32(smem);
    const int tid = threadIdx.x;
    const int wid = tid >> 5, lane = tid & 31;

    const int isJ1 = (blockIdx.x >= splitX);
    const GJob j = isJ1 ? j1 : j0;
    const int nx = blockIdx.x - (isJ1 ? splitX : 0);
    const int m0 = blockIdx.y * BM, n0 = nx * 128;
    const int warpM = (wid >> 2) * (BM / 2);
    const int warpN = (wid & 3) * 32;

    const uint32_t aOff = (warpM + (lane & 15)) * 80 + (lane >> 4) * 16;
    const uint32_t bOff = (warpN + (lane & 7) + ((lane >> 4) & 1) * 8) * 80
                        + ((lane >> 3) & 1) * 16;

    float acc[MT][4][4];
#pragma unroll
    for (int i = 0; i < MT; i++)
#pragma unroll
        for (int jt = 0; jt < 4; jt++)
#pragma unroll
            for (int q = 0; q < 4; q++) acc[i][jt][q] = 0.f;

    const int NC = K >> 5;

    // prologue: fill STAGES-1 stages (always commit so group counting is uniform)
#pragma unroll
    for (int s = 0; s < STAGES - 1; s++) {
        if (s < NC) load_stage<BM>(sb + s * STAGE, j, m0, n0, s * 32, tid, K);
        CP_COMMIT();
    }

    for (int c = 0; c < NC; c++) {
        asm volatile("cp.async.wait_group %0;" :: "n"(STAGES - 2) : "memory");
        __syncthreads();

        int pf = c + STAGES - 1;
        if (pf < NC) load_stage<BM>(sb + (pf % STAGES) * STAGE, j, m0, n0, pf * 32, tid, K);
        CP_COMMIT();

        const uint32_t st = sb + (c % STAGES) * STAGE;
#pragma unroll
        for (int ks = 0; ks < 2; ks++) {
            uint32_t ah[MT][4], al[MT][4], bh[2][4], bl[2][4];
#pragma unroll
            for (int mt = 0; mt < MT; mt++) {
                uint32_t ad = st + aOff + mt * (16 * 80) + ks * 32;
                LDSM4(ah[mt], ad);
                LDSM4(al[mt], ad + MAT_A);
            }
#pragma unroll
            for (int np = 0; np < 2; np++) {
                uint32_t bd = st + OFF_B + bOff + np * (16 * 80) + ks * 32;
                LDSM4(bh[np], bd);
                LDSM4(bl[np], bd + 10240);
            }
            // 3 term-passes: consecutive MMAs hit different accumulators
            // (16-MMA reuse distance instead of back-to-back RAW chains)
#pragma unroll
            for (int mt = 0; mt < MT; mt++)
#pragma unroll
                for (int nt = 0; nt < 4; nt++)
                    MMA16816(acc[mt][nt], ah[mt], (&bh[nt >> 1][(nt & 1) * 2]));
#pragma unroll
            for (int mt = 0; mt < MT; mt++)
#pragma unroll
                for (int nt = 0; nt < 4; nt++)
                    MMA16816(acc[mt][nt], ah[mt], (&bl[nt >> 1][(nt & 1) * 2]));
#pragma unroll
            for (int mt = 0; mt < MT; mt++)
#pragma unroll
                for (int nt = 0; nt < 4; nt++)
                    MMA16816(acc[mt][nt], al[mt], (&bh[nt >> 1][(nt & 1) * 2]));
        }
    }

    // ---------------- epilogue ----------------
    const int lr = lane >> 2;
    const int lc = (lane & 3) * 2;
#pragma unroll
    for (int mt = 0; mt < MT; mt++) {
        int grow = m0 + warpM + mt * 16 + lr;
        int lab0 = 0, lab1 = 0;
        if (j.rowTab) { lab0 = j.rowLab[grow]; lab1 = j.rowLab[grow + 8]; }
#pragma unroll
        for (int nt = 0; nt < 4; nt++) {
            int gcol = n0 + warpN + nt * 8 + lc;
            float v0 = acc[mt][nt][0], v1 = acc[mt][nt][1];
            float v2 = acc[mt][nt][2], v3 = acc[mt][nt][3];
            if (j.bias) {
                float b0v = __ldg(j.bias + gcol), b1v = __ldg(j.bias + gcol + 1);
                v0 += b0v; v1 += b1v; v2 += b0v; v3 += b1v;
            }
            if (j.rowTab) {
                v0 += __ldg(j.rowTab + (size_t)lab0 * j.ldTab + gcol);
                v1 += __ldg(j.rowTab + (size_t)lab0 * j.ldTab + gcol + 1);
                v2 += __ldg(j.rowTab + (size_t)lab1 * j.ldTab + gcol);
                v3 += __ldg(j.rowTab + (size_t)lab1 * j.ldTab + gcol + 1);
            }
            if (j.relu) {
                v0 = fmaxf(v0, 0.f); v1 = fmaxf(v1, 0.f);
                v2 = fmaxf(v2, 0.f); v3 = fmaxf(v3, 0.f);
            }
            if (j.outF) {
                *(float2*)(j.outF + (size_t)grow * j.ldo + gcol)       = make_float2(v0, v1);
                *(float2*)(j.outF + (size_t)(grow + 8) * j.ldo + gcol) = make_float2(v2, v3);
            }
            if (j.outH) {
                __nv_bfloat16 h0, l0, h1, l1, h2, l2, h3, l3;
                split2(v0, h0, l0); split2(v1, h1, l1);
                split2(v2, h2, l2); split2(v3, h3, l3);
                *(__nv_bfloat162*)(j.outH + (size_t)grow * j.ldo + gcol)       = __nv_bfloat162(h0, h1);
                *(__nv_bfloat162*)(j.outL + (size_t)grow * j.ldo + gcol)       = __nv_bfloat162(l0, l1);
                *(__nv_bfloat162*)(j.outH + (size_t)(grow + 8) * j.ldo + gcol) = __nv_bfloat162(h2, h3);
                *(__nv_bfloat162*)(j.outL + (size_t)(grow + 8) * j.ldo + gcol) = __nv_bfloat162(l2, l3);
            }
        }
    }
}

// ---------------- per-entity linear terms ----------------
__global__ void lin_kernel(const float* __restrict__ lW) {
    int m = blockIdx.x;
    int warp = threadIdx.x >> 5;
    int lane = threadIdx.x & 31;
    const float* src = (warp == 0) ? (g_eH + (size_t)m * HH2) : (g_eT + (size_t)m * HH2);
    int wbase = warp * HH2;
    float a0 = 0.f, a1 = 0.f;
    for (int i = lane; i < HH2; i += 32) {
        float x = src[i];
        a0 = fmaf(x, lW[(wbase + i) * 2 + 0], a0);
        a1 = fmaf(x, lW[(wbase + i) * 2 + 1], a1);
    }
#pragma unroll
    for (int off = 16; off; off >>= 1) {
        a0 += __shfl_xor_sync(0xffffffffu, a0, off);
        a1 += __shfl_xor_sync(0xffffffffu, a1, off);
    }
    if (lane == 0) {
        float* dst = (warp == 0) ? g_hlin : g_tlin;
        dst[m * 2 + 0] = a0;
        dst[m * 2 + 1] = a1;
    }
}

// ---------------- per-relation logits + NLL partials (float4-vectorized) ----------------
__global__ void rel_kernel(const int* __restrict__ rel_head, const int* __restrict__ rel_tail,
                           const int* __restrict__ rel_label, const float* __restrict__ lb,
                           float* __restrict__ out_logits) {
    int warp = threadIdx.x >> 5;
    int lane = threadIdx.x & 31;
    int r = blockIdx.x * 8 + warp;
    int b = r / RR;
    int hidx = rel_head[r];
    int tidx = rel_tail[r];
    size_t hm = (size_t)(b * EE + hidx);
    size_t tm = (size_t)(b * EE + tidx);
    const float4* hb4 = (const float4*)(g_hb + hm * (2 * HH2));
    const float4* t4  = (const float4*)(g_eT + tm * HH2);
    float a0 = 0.f, a1 = 0.f;
#pragma unroll
    for (int i = 0; i < 3; i++) {
        int jx = i * 32 + lane;
        float4 t = t4[jx];
        float4 h0 = hb4[jx];
        float4 h1 = hb4[96 + jx];
        a0 = fmaf(h0.x, t.x, a0); a0 = fmaf(h0.y, t.y, a0);
        a0 = fmaf(h0.z, t.z, a0); a0 = fmaf(h0.w, t.w, a0);
        a1 = fmaf(h1.x, t.x, a1); a1 = fmaf(h1.y, t.y, a1);
        a1 = fmaf(h1.z, t.z, a1); a1 = fmaf(h1.w, t.w, a1);
    }
#pragma unroll
    for (int off = 16; off; off >>= 1) {
        a0 += __shfl_xor_sync(0xffffffffu, a0, off);
        a1 += __shfl_xor_sync(0xffffffffu, a1, off);
    }
    __shared__ float sloss[8];
    if (lane == 0) {
        float l0 = a0 + g_hlin[hm * 2 + 0] + g_tlin[tm * 2 + 0] + lb[0];
        float l1 = a1 + g_hlin[hm * 2 + 1] + g_tlin[tm * 2 + 1] + lb[1];
        out_logits[(size_t)r * 2 + 0] = l0;
        out_logits[(size_t)r * 2 + 1] = l1;
        float mx = fmaxf(l0, l1);
        float lse = mx + logf(expf(l0 - mx) + expf(l1 - mx));
        int lab = rel_label[r];
        sloss[warp] = (lab ? l1 : l0) - lse;
    }
    __syncthreads();
    if (threadIdx.x == 0) {
        float s = 0.f;
#pragma unroll
        for (int i = 0; i < 8; i++) s += sloss[i];
        g_partials[blockIdx.x] = s;
    }
}

__global__ void loss_reduce_kernel(float* __restrict__ out_loss) {
    __shared__ float sh[256];
    float s = 0.f;
    for (int i = threadIdx.x; i < RELBLOCKS; i += 256) s += g_partials[i];
    sh[threadIdx.x] = s;
    __syncthreads();
    for (int off = 128; off; off >>= 1) {
        if (threadIdx.x < off) sh[threadIdx.x] += sh[threadIdx.x + off];
        __syncthreads();
    }
    if (threadIdx.x == 0) *out_loss = -sh[0] / (float)NREL;
}

// ---------------- host launch ----------------
#define SMEM128 (4 * (2 * 128 * 80 + 20480))   // 163840, 4 stages, 1 CTA/SM
#define SMEM64  (3 * (2 * 64 * 80 + 20480))    // 92160, 3 stages, 2 CTA/SM

extern "C" void kernel_launch(void* const* d_in, const int* in_sizes, int n_in,
                              void* d_out, int out_size) {
    const float* hs        = (const float*)d_in[0];
    const float* emb       = (const float*)d_in[1];
    const float* hW1       = (const float*)d_in[2];
    const float* hb1       = (const float*)d_in[3];
    const float* hW2       = (const float*)d_in[4];
    const float* hb2       = (const float*)d_in[5];
    const float* tW1       = (const float*)d_in[6];
    const float* tb1       = (const float*)d_in[7];
    const float* tW2       = (const float*)d_in[8];
    const float* tb2       = (const float*)d_in[9];
    const float* bil_w     = (const float*)d_in[10];
    const float* lW        = (const float*)d_in[11];
    const float* lb        = (const float*)d_in[12];
    const int*   ent_start = (const int*)d_in[13];
    const int*   ent_label = (const int*)d_in[14];
    const int*   rel_head  = (const int*)d_in[15];
    const int*   rel_tail  = (const int*)d_in[16];
    const int*   rel_label = (const int*)d_in[17];

    cudaFuncSetAttribute(mma_gemm<128, 4, 1>, cudaFuncAttributeMaxDynamicSharedMemorySize, SMEM128);
    cudaFuncSetAttribute(mma_gemm<64,  3, 2>, cudaFuncAttributeMaxDynamicSharedMemorySize, SMEM64);

    __nv_bfloat16 *p_repH, *p_repL, *p_w1H, *p_w1L, *p_h1H, *p_h1L;
    __nv_bfloat16 *p_w2hH, *p_w2hL, *p_w2tH, *p_w2tL, *p_eHH, *p_eHL, *p_bilH, *p_bilL;
    float *p_eH, *p_eT, *p_hb, *p_embW1;
    cudaGetSymbolAddress((void**)&p_repH, g_repH); cudaGetSymbolAddress((void**)&p_repL, g_repL);
    cudaGetSymbolAddress((void**)&p_w1H,  g_w1H ); cudaGetSymbolAddress((void**)&p_w1L,  g_w1L );
    cudaGetSymbolAddress((void**)&p_h1H,  g_h1H ); cudaGetSymbolAddress((void**)&p_h1L,  g_h1L );
    cudaGetSymbolAddress((void**)&p_w2hH, g_w2hH); cudaGetSymbolAddress((void**)&p_w2hL, g_w2hL);
    cudaGetSymbolAddress((void**)&p_w2tH, g_w2tH); cudaGetSymbolAddress((void**)&p_w2tL, g_w2tL);
    cudaGetSymbolAddress((void**)&p_eHH,  g_eHH ); cudaGetSymbolAddress((void**)&p_eHL,  g_eHL );
    cudaGetSymbolAddress((void**)&p_bilH, g_bilH); cudaGetSymbolAddress((void**)&p_bilL, g_bilL);
    cudaGetSymbolAddress((void**)&p_eH,   g_eH  ); cudaGetSymbolAddress((void**)&p_eT,   g_eT  );
    cudaGetSymbolAddress((void**)&p_hb,   g_hb  ); cudaGetSymbolAddress((void**)&p_embW1, g_embW1);

    const int logit_elems = NREL * 2;
    int off = out_size - logit_elems;
    if (off < 0) off = 0;
    float* logits_out = (float*)d_out + off;

    // 1) independent prep
    gather_kernel<<<ME, 256>>>(hs, ent_start);
    embw1_kernel<<<576, 256>>>(emb, hW1, hb1, tW1, tb1);
    wconv_all<<<2016, dim3(32, 8)>>>(hW1, tW1, hW2, tW2, bil_w);

    // 2) layer 1 (fused head|tail): [2048,768] x [1536,768]^T + embW1[label], relu
    {
        GJob j = {};
        j.aH = p_repH; j.aL = p_repL; j.lda = DD;
        j.bH = p_w1H;  j.bL = p_w1L;
        j.rowTab = p_embW1; j.rowLab = ent_label; j.ldTab = N1;
        j.outH = p_h1H; j.outL = p_h1L; j.ldo = N1;
        j.relu = 1;
        mma_gemm<128, 4, 1><<<dim3(N1 / 128, ME / 128), 256, SMEM128>>>(j, j, 999, DD);
    }
    // 3) layer 2 merged (head + tail towers), BM=64, 192 CTAs, 2 CTA/SM
    {
        GJob jh = {}, jt = {};
        jh.aH = p_h1H;      jh.aL = p_h1L;      jh.lda = N1;
        jh.bH = p_w2hH;     jh.bL = p_w2hL;
        jh.bias = hb2;
        jh.outH = p_eHH; jh.outL = p_eHL; jh.outF = p_eH; jh.ldo = HH2;
        jh.relu = 1;
        jt.aH = p_h1H + HH; jt.aL = p_h1L + HH; jt.lda = N1;
        jt.bH = p_w2tH;     jt.bL = p_w2tL;
        jt.bias = tb2;
        jt.outF = p_eT; jt.ldo = HH2;
        jt.relu = 1;
        mma_gemm<64, 3, 2><<<dim3(6, ME / 64), 256, SMEM64>>>(jh, jt, 3, HH);
    }
    // 4) bilinear precompute, BM=64, 192 CTAs, 2 CTA/SM
    {
        GJob j = {};
        j.aH = p_eHH; j.aL = p_eHL; j.lda = HH2;
        j.bH = p_bilH; j.bL = p_bilL;
        j.outF = p_hb; j.ldo = 2 * HH2;
        j.relu = 0;
        mma_gemm<64, 3, 2><<<dim3(2 * HH2 / 128, ME / 64), 256, SMEM64>>>(j, j, 999, HH2);
    }

    // 5) per-entity linear terms
    lin_kernel<<<ME, 64>>>(lW);

    // 6) per-relation logits + loss partials
    rel_kernel<<<RELBLOCKS, 256>>>(rel_head, rel_tail, rel_label, lb, logits_out);

    // 7) loss
    if (off >= 1) loss_reduce_kernel<<<1, 256>>>((float*)d_out);
}

// round 12
// speedup vs baseline: 1.6000x; 1.6000x over previous
#include <cuda_runtime.h>
#include <cuda_bf16.h>
#include <stdint.h>
#include <math.h>

// ---------------- problem constants ----------------
#define BB   16
#define SS_  512
#define DD   768
#define EE   128
#define RR   2048
#define HH   768
#define HH2  384
#define ME   (BB * EE)        // 2048 entity rows
#define NREL (BB * RR)        // 32768 relations
#define RELBLOCKS (NREL / 8)
#define N1   (2 * HH)         // 1536 (head|tail fused layer1 output)

// ---------------- scratch (static device globals) ----------------
__device__ __nv_bfloat16 g_repH[ME * DD],  g_repL[ME * DD];
__device__ __nv_bfloat16 g_w1H [N1 * DD],  g_w1L [N1 * DD];
__device__ __nv_bfloat16 g_h1H [ME * N1],  g_h1L [ME * N1];
__device__ __nv_bfloat16 g_w2hH[HH2 * HH], g_w2hL[HH2 * HH];
__device__ __nv_bfloat16 g_w2tH[HH2 * HH], g_w2tL[HH2 * HH];
__device__ __nv_bfloat16 g_eHH [ME * HH2], g_eHL [ME * HH2];
__device__ __nv_bfloat16 g_bilH[2 * HH2 * HH2], g_bilL[2 * HH2 * HH2];
__device__ float g_embW1[3 * N1];
__device__ float g_eH[ME * HH2], g_eT[ME * HH2];
__device__ float g_hb[ME * 2 * HH2];
__device__ float g_hlin[ME * 2], g_tlin[ME * 2];
__device__ float g_partials[RELBLOCKS];

// ---------------- helpers ----------------
__device__ __forceinline__ uint32_t smem_u32(const void* p) {
    uint32_t a;
    asm("{ .reg .u64 t; cvta.to.shared.u64 t, %1; cvt.u32.u64 %0, t; }" : "=r"(a) : "l"(p));
    return a;
}
__device__ __forceinline__ void cpa16(uint32_t dst, const void* src) {
    asm volatile("cp.async.cg.shared.global [%0], [%1], 16;" :: "r"(dst), "l"(src));
}
#define CP_COMMIT() asm volatile("cp.async.commit_group;" ::: "memory")

#define LDSM4(r, addr) \
    asm volatile("ldmatrix.sync.aligned.m8n8.x4.shared.b16 {%0,%1,%2,%3}, [%4];" \
        : "=r"((r)[0]), "=r"((r)[1]), "=r"((r)[2]), "=r"((r)[3]) : "r"(addr))

#define MMA16816(d, a, b) \
    asm volatile("mma.sync.aligned.m16n8k16.row.col.f32.bf16.bf16.f32 " \
        "{%0,%1,%2,%3}, {%4,%5,%6,%7}, {%8,%9}, {%0,%1,%2,%3};" \
        : "+f"((d)[0]), "+f"((d)[1]), "+f"((d)[2]), "+f"((d)[3]) \
        : "r"((a)[0]), "r"((a)[1]), "r"((a)[2]), "r"((a)[3]), "r"((b)[0]), "r"((b)[1]))

__device__ __forceinline__ void split2(float x, __nv_bfloat16& h, __nv_bfloat16& l) {
    h = __float2bfloat16(x);
    l = __float2bfloat16(x - __bfloat162float(h));
}

// ---------------- gather + convert (hid part only) ----------------
__global__ void gather_kernel(const float* __restrict__ hs,
                              const int* __restrict__ es) {
    int m = blockIdx.x;
    int b = m >> 7;
    int s = es[m];
    const float* src = hs + ((size_t)b * SS_ + s) * DD;
    size_t rb = (size_t)m * DD;
    for (int i = threadIdx.x; i < DD; i += 256) {
        __nv_bfloat16 h, l;
        split2(src[i], h, l);
        g_repH[rb + i] = h; g_repL[rb + i] = l;
    }
}

// ---------------- embW1[l, n] = emb[l] @ W1_bottom[:, n] + b1[n]  (exact fp32) ----------------
__global__ void embw1_kernel(const float* __restrict__ emb,
                             const float* __restrict__ hW1, const float* __restrict__ hb1,
                             const float* __restrict__ tW1, const float* __restrict__ tb1) {
    int o = blockIdx.x * 8 + (threadIdx.x >> 5);
    int lane = threadIdx.x & 31;
    int l = o / N1, n = o % N1;
    const float* er = emb + (size_t)l * DD;
    const float* w;
    float bias;
    if (n < HH) { w = hW1 + (size_t)DD * HH + n;        bias = hb1[n]; }
    else        { w = tW1 + (size_t)DD * HH + (n - HH); bias = tb1[n - HH]; }
    float a = 0.f;
    for (int k = lane; k < DD; k += 32) a = fmaf(er[k], w[(size_t)k * HH], a);
#pragma unroll
    for (int off = 16; off; off >>= 1) a += __shfl_xor_sync(0xffffffffu, a, off);
    if (lane == 0) g_embW1[o] = a + bias;
}

// ---------------- all weight transposes+converts in ONE launch ----------------
__global__ void wconv_all(const float* __restrict__ hW1, const float* __restrict__ tW1,
                          const float* __restrict__ hW2, const float* __restrict__ tW2,
                          const float* __restrict__ bil) {
    __shared__ float t[32][33];
    int id = blockIdx.x;
    const float* W; int K, N; __nv_bfloat16 *oH, *oL;
    if (id < 576)       { W = hW1;             K = 768; N = 768; oH = g_w1H;             oL = g_w1L; }
    else if (id < 1152) { W = tW1;             K = 768; N = 768; oH = g_w1H + 768 * 768; oL = g_w1L + 768 * 768; id -= 576; }
    else if (id < 1440) { W = hW2;             K = 768; N = 384; oH = g_w2hH;            oL = g_w2hL; id -= 1152; }
    else if (id < 1728) { W = tW2;             K = 768; N = 384; oH = g_w2tH;            oL = g_w2tL; id -= 1440; }
    else if (id < 1872) { W = bil;             K = 384; N = 384; oH = g_bilH;            oL = g_bilL; id -= 1728; }
    else                { W = bil + 384 * 384; K = 384; N = 384; oH = g_bilH + 384 * 384; oL = g_bilL + 384 * 384; id -= 1872; }
    int ntiles = N / 32;
    int n0 = (id % ntiles) * 32, k0 = (id / ntiles) * 32;
    int tx = threadIdx.x, ty = threadIdx.y;
#pragma unroll
    for (int j = 0; j < 32; j += 8)
        t[ty + j][tx] = W[(size_t)(k0 + ty + j) * N + n0 + tx];
    __syncthreads();
#pragma unroll
    for (int j = 0; j < 32; j += 8) {
        int n = n0 + ty + j, k = k0 + tx;
        __nv_bfloat16 h, l;
        split2(t[tx][ty + j], h, l);
        oH[(size_t)n * K + k] = h;
        oL[(size_t)n * K + k] = l;
    }
}

// ---------------- mma.sync split-bf16 GEMM, 2-stage cp.async, 2 CTAs/SM ----------------
struct GJob {
    const __nv_bfloat16 *aH, *aL; int lda;
    const __nv_bfloat16 *bH, *bL;            // ldb = K
    const float* bias;
    const float* rowTab; const int* rowLab; int ldTab;
    __nv_bfloat16 *outH, *outL;
    float* outF;
    int ldo;
    int relu;
};

template <int BM>
__device__ __forceinline__ void load_stage(uint32_t sbase, const GJob& j,
                                           int m0, int n0, int k0, int tid, int K) {
    const int ACH = BM * 4;                  // 16B chunks per A matrix
#pragma unroll
    for (int idx = tid; idx < 2 * ACH + 1024; idx += 256) {
        if (idx < ACH) {
            int row = idx >> 2, ch = idx & 3;
            cpa16(sbase + row * 80 + ch * 16, j.aH + (size_t)(m0 + row) * j.lda + k0 + ch * 8);
        } else if (idx < 2 * ACH) {
            int q = idx - ACH; int row = q >> 2, ch = q & 3;
            cpa16(sbase + BM * 80 + row * 80 + ch * 16, j.aL + (size_t)(m0 + row) * j.lda + k0 + ch * 8);
        } else if (idx < 2 * ACH + 512) {
            int q = idx - 2 * ACH; int row = q >> 2, ch = q & 3;
            cpa16(sbase + 2 * BM * 80 + row * 80 + ch * 16, j.bH + (size_t)(n0 + row) * K + k0 + ch * 8);
        } else {
            int q = idx - 2 * ACH - 512; int row = q >> 2, ch = q & 3;
            cpa16(sbase + 2 * BM * 80 + 10240 + row * 80 + ch * 16, j.bL + (size_t)(n0 + row) * K + k0 + ch * 8);
        }
    }
}

template <int BM>
__global__ void __launch_bounds__(256, 2)
mma_gemm(GJob j0, GJob j1, int splitX, int K) {
    constexpr int MT = BM / 32;
    constexpr int MAT_A = BM * 80;
    constexpr int OFF_B = 2 * BM * 80;
    constexpr int STAGE = 2 * BM * 80 + 20480;
    extern __shared__ char smem[];
    const uint32_t sb = smem_u32(smem);
    const int tid = threadIdx.x;
    const int wid = tid >> 5, lane = tid & 31;

    const int isJ1 = (blockIdx.x >= splitX);
    const GJob j = isJ1 ? j1 : j0;
    const int nx = blockIdx.x - (isJ1 ? splitX : 0);
    const int m0 = blockIdx.y * BM, n0 = nx * 128;
    const int warpM = (wid >> 2) * (BM / 2);
    const int warpN = (wid & 3) * 32;

    const uint32_t aOff = (warpM + (lane & 15)) * 80 + (lane >> 4) * 16;
    const uint32_t bOff = (warpN + (lane & 7) + ((lane >> 4) & 1) * 8) * 80
                        + ((lane >> 3) & 1) * 16;

    float acc[MT][4][4];
#pragma unroll
    for (int i = 0; i < MT; i++)
#pragma unroll
        for (int jt = 0; jt < 4; jt++)
#pragma unroll
            for (int q = 0; q < 4; q++) acc[i][jt][q] = 0.f;

    const int NC = K >> 5;

    load_stage<BM>(sb, j, m0, n0, 0, tid, K);
    CP_COMMIT();

    for (int c = 0; c < NC; c++) {
        asm volatile("cp.async.wait_group 0;" ::: "memory");
        __syncthreads();

        if (c + 1 < NC) {
            load_stage<BM>(sb + ((c + 1) & 1) * STAGE, j, m0, n0, (c + 1) * 32, tid, K);
            CP_COMMIT();
        }

        const uint32_t st = sb + (c & 1) * STAGE;
#pragma unroll
        for (int ks = 0; ks < 2; ks++) {
            uint32_t bh[2][4], bl[2][4];
#pragma unroll
            for (int np = 0; np < 2; np++) {
                uint32_t bd = st + OFF_B + bOff + np * (16 * 80) + ks * 32;
                LDSM4(bh[np], bd);
                LDSM4(bl[np], bd + 10240);
            }
            // per-mt A fragments (keeps live frag regs at 24: fits 2 CTAs/SM)
#pragma unroll
            for (int mt = 0; mt < MT; mt++) {
                uint32_t ah[4], al[4];
                uint32_t ad = st + aOff + mt * (16 * 80) + ks * 32;
                LDSM4(ah, ad);
                LDSM4(al, ad + MAT_A);
                // 3 nt-passes: 4 independent accumulator chains per pass
#pragma unroll
                for (int nt = 0; nt < 4; nt++)
                    MMA16816(acc[mt][nt], ah, (&bh[nt >> 1][(nt & 1) * 2]));
#pragma unroll
                for (int nt = 0; nt < 4; nt++)
                    MMA16816(acc[mt][nt], ah, (&bl[nt >> 1][(nt & 1) * 2]));
#pragma unroll
                for (int nt = 0; nt < 4; nt++)
                    MMA16816(acc[mt][nt], al, (&bh[nt >> 1][(nt & 1) * 2]));
            }
        }
        __syncthreads();
    }

    // ---------------- epilogue ----------------
    const int lr = lane >> 2;
    const int lc = (lane & 3) * 2;
#pragma unroll
    for (int mt = 0; mt < MT; mt++) {
        int grow = m0 + warpM + mt * 16 + lr;
        int lab0 = 0, lab1 = 0;
        if (j.rowTab) { lab0 = j.rowLab[grow]; lab1 = j.rowLab[grow + 8]; }
#pragma unroll
        for (int nt = 0; nt < 4; nt++) {
            int gcol = n0 + warpN + nt * 8 + lc;
            float v0 = acc[mt][nt][0], v1 = acc[mt][nt][1];
            float v2 = acc[mt][nt][2], v3 = acc[mt][nt][3];
            if (j.bias) {
                float b0v = __ldg(j.bias + gcol), b1v = __ldg(j.bias + gcol + 1);
                v0 += b0v; v1 += b1v; v2 += b0v; v3 += b1v;
            }
            if (j.rowTab) {
                v0 += __ldg(j.rowTab + (size_t)lab0 * j.ldTab + gcol);
                v1 += __ldg(j.rowTab + (size_t)lab0 * j.ldTab + gcol + 1);
                v2 += __ldg(j.rowTab + (size_t)lab1 * j.ldTab + gcol);
                v3 += __ldg(j.rowTab + (size_t)lab1 * j.ldTab + gcol + 1);
            }
            if (j.relu) {
                v0 = fmaxf(v0, 0.f); v1 = fmaxf(v1, 0.f);
                v2 = fmaxf(v2, 0.f); v3 = fmaxf(v3, 0.f);
            }
            if (j.outF) {
                *(float2*)(j.outF + (size_t)grow * j.ldo + gcol)       = make_float2(v0, v1);
                *(float2*)(j.outF + (size_t)(grow + 8) * j.ldo + gcol) = make_float2(v2, v3);
            }
            if (j.outH) {
                __nv_bfloat16 h0, l0, h1, l1, h2, l2, h3, l3;
                split2(v0, h0, l0); split2(v1, h1, l1);
                split2(v2, h2, l2); split2(v3, h3, l3);
                *(__nv_bfloat162*)(j.outH + (size_t)grow * j.ldo + gcol)       = __nv_bfloat162(h0, h1);
                *(__nv_bfloat162*)(j.outL + (size_t)grow * j.ldo + gcol)       = __nv_bfloat162(l0, l1);
                *(__nv_bfloat162*)(j.outH + (size_t)(grow + 8) * j.ldo + gcol) = __nv_bfloat162(h2, h3);
                *(__nv_bfloat162*)(j.outL + (size_t)(grow + 8) * j.ldo + gcol) = __nv_bfloat162(l2, l3);
            }
        }
    }
}

// ---------------- per-entity linear terms ----------------
__global__ void lin_kernel(const float* __restrict__ lW) {
    int m = blockIdx.x;
    int warp = threadIdx.x >> 5;
    int lane = threadIdx.x & 31;
    const float* src = (warp == 0) ? (g_eH + (size_t)m * HH2) : (g_eT + (size_t)m * HH2);
    int wbase = warp * HH2;
    float a0 = 0.f, a1 = 0.f;
    for (int i = lane; i < HH2; i += 32) {
        float x = src[i];
        a0 = fmaf(x, lW[(wbase + i) * 2 + 0], a0);
        a1 = fmaf(x, lW[(wbase + i) * 2 + 1], a1);
    }
#pragma unroll
    for (int off = 16; off; off >>= 1) {
        a0 += __shfl_xor_sync(0xffffffffu, a0, off);
        a1 += __shfl_xor_sync(0xffffffffu, a1, off);
    }
    if (lane == 0) {
        float* dst = (warp == 0) ? g_hlin : g_tlin;
        dst[m * 2 + 0] = a0;
        dst[m * 2 + 1] = a1;
    }
}

// ---------------- per-relation logits + NLL partials (float4-vectorized) ----------------
__global__ void rel_kernel(const int* __restrict__ rel_head, const int* __restrict__ rel_tail,
                           const int* __restrict__ rel_label, const float* __restrict__ lb,
                           float* __restrict__ out_logits) {
    int warp = threadIdx.x >> 5;
    int lane = threadIdx.x & 31;
    int r = blockIdx.x * 8 + warp;
    int b = r / RR;
    int hidx = rel_head[r];
    int tidx = rel_tail[r];
    size_t hm = (size_t)(b * EE + hidx);
    size_t tm = (size_t)(b * EE + tidx);
    const float4* hb4 = (const float4*)(g_hb + hm * (2 * HH2));
    const float4* t4  = (const float4*)(g_eT + tm * HH2);
    float a0 = 0.f, a1 = 0.f;
#pragma unroll
    for (int i = 0; i < 3; i++) {
        int jx = i * 32 + lane;
        float4 t = t4[jx];
        float4 h0 = hb4[jx];
        float4 h1 = hb4[96 + jx];
        a0 = fmaf(h0.x, t.x, a0); a0 = fmaf(h0.y, t.y, a0);
        a0 = fmaf(h0.z, t.z, a0); a0 = fmaf(h0.w, t.w, a0);
        a1 = fmaf(h1.x, t.x, a1); a1 = fmaf(h1.y, t.y, a1);
        a1 = fmaf(h1.z, t.z, a1); a1 = fmaf(h1.w, t.w, a1);
    }
#pragma unroll
    for (int off = 16; off; off >>= 1) {
        a0 += __shfl_xor_sync(0xffffffffu, a0, off);
        a1 += __shfl_xor_sync(0xffffffffu, a1, off);
    }
    __shared__ float sloss[8];
    if (lane == 0) {
        float l0 = a0 + g_hlin[hm * 2 + 0] + g_tlin[tm * 2 + 0] + lb[0];
        float l1 = a1 + g_hlin[hm * 2 + 1] + g_tlin[tm * 2 + 1] + lb[1];
        out_logits[(size_t)r * 2 + 0] = l0;
        out_logits[(size_t)r * 2 + 1] = l1;
        float mx = fmaxf(l0, l1);
        float lse = mx + logf(expf(l0 - mx) + expf(l1 - mx));
        int lab = rel_label[r];
        sloss[warp] = (lab ? l1 : l0) - lse;
    }
    __syncthreads();
    if (threadIdx.x == 0) {
        float s = 0.f;
#pragma unroll
        for (int i = 0; i < 8; i++) s += sloss[i];
        g_partials[blockIdx.x] = s;
    }
}

__global__ void loss_reduce_kernel(float* __restrict__ out_loss) {
    __shared__ float sh[256];
    float s = 0.f;
    for (int i = threadIdx.x; i < RELBLOCKS; i += 256) s += g_partials[i];
    sh[threadIdx.x] = s;
    __syncthreads();
    for (int off = 128; off; off >>= 1) {
        if (threadIdx.x < off) sh[threadIdx.x] += sh[threadIdx.x + off];
        __syncthreads();
    }
    if (threadIdx.x == 0) *out_loss = -sh[0] / (float)NREL;
}

// ---------------- host launch ----------------
#define SMEM128 (2 * (2 * 128 * 80 + 20480))   // 81920/CTA -> 2 CTAs/SM
#define SMEM64  (2 * (2 * 64 * 80 + 20480))    // 61440/CTA -> 2 CTAs/SM

extern "C" void kernel_launch(void* const* d_in, const int* in_sizes, int n_in,
                              void* d_out, int out_size) {
    const float* hs        = (const float*)d_in[0];
    const float* emb       = (const float*)d_in[1];
    const float* hW1       = (const float*)d_in[2];
    const float* hb1       = (const float*)d_in[3];
    const float* hW2       = (const float*)d_in[4];
    const float* hb2       = (const float*)d_in[5];
    const float* tW1       = (const float*)d_in[6];
    const float* tb1       = (const float*)d_in[7];
    const float* tW2       = (const float*)d_in[8];
    const float* tb2       = (const float*)d_in[9];
    const float* bil_w     = (const float*)d_in[10];
    const float* lW        = (const float*)d_in[11];
    const float* lb        = (const float*)d_in[12];
    const int*   ent_start = (const int*)d_in[13];
    const int*   ent_label = (const int*)d_in[14];
    const int*   rel_head  = (const int*)d_in[15];
    const int*   rel_tail  = (const int*)d_in[16];
    const int*   rel_label = (const int*)d_in[17];

    cudaFuncSetAttribute(mma_gemm<128>, cudaFuncAttributeMaxDynamicSharedMemorySize, SMEM128);
    cudaFuncSetAttribute(mma_gemm<64>,  cudaFuncAttributeMaxDynamicSharedMemorySize, SMEM64);

    __nv_bfloat16 *p_repH, *p_repL, *p_w1H, *p_w1L, *p_h1H, *p_h1L;
    __nv_bfloat16 *p_w2hH, *p_w2hL, *p_w2tH, *p_w2tL, *p_eHH, *p_eHL, *p_bilH, *p_bilL;
    float *p_eH, *p_eT, *p_hb, *p_embW1;
    cudaGetSymbolAddress((void**)&p_repH, g_repH); cudaGetSymbolAddress((void**)&p_repL, g_repL);
    cudaGetSymbolAddress((void**)&p_w1H,  g_w1H ); cudaGetSymbolAddress((void**)&p_w1L,  g_w1L );
    cudaGetSymbolAddress((void**)&p_h1H,  g_h1H ); cudaGetSymbolAddress((void**)&p_h1L,  g_h1L );
    cudaGetSymbolAddress((void**)&p_w2hH, g_w2hH); cudaGetSymbolAddress((void**)&p_w2hL, g_w2hL);
    cudaGetSymbolAddress((void**)&p_w2tH, g_w2tH); cudaGetSymbolAddress((void**)&p_w2tL, g_w2tL);
    cudaGetSymbolAddress((void**)&p_eHH,  g_eHH ); cudaGetSymbolAddress((void**)&p_eHL,  g_eHL );
    cudaGetSymbolAddress((void**)&p_bilH, g_bilH); cudaGetSymbolAddress((void**)&p_bilL, g_bilL);
    cudaGetSymbolAddress((void**)&p_eH,   g_eH  ); cudaGetSymbolAddress((void**)&p_eT,   g_eT  );
    cudaGetSymbolAddress((void**)&p_hb,   g_hb  ); cudaGetSymbolAddress((void**)&p_embW1, g_embW1);

    const int logit_elems = NREL * 2;
    int off = out_size - logit_elems;
    if (off < 0) off = 0;
    float* logits_out = (float*)d_out + off;

    // 1) independent prep
    gather_kernel<<<ME, 256>>>(hs, ent_start);
    embw1_kernel<<<576, 256>>>(emb, hW1, hb1, tW1, tb1);
    wconv_all<<<2016, dim3(32, 8)>>>(hW1, tW1, hW2, tW2, bil_w);

    // 2) layer 1 (fused head|tail): [2048,768] x [1536,768]^T + embW1[label], relu
    {
        GJob j = {};
        j.aH = p_repH; j.aL = p_repL; j.lda = DD;
        j.bH = p_w1H;  j.bL = p_w1L;
        j.rowTab = p_embW1; j.rowLab = ent_label; j.ldTab = N1;
        j.outH = p_h1H; j.outL = p_h1L; j.ldo = N1;
        j.relu = 1;
        mma_gemm<128><<<dim3(N1 / 128, ME / 128), 256, SMEM128>>>(j, j, 999, DD);
    }
    // 3) layer 2 merged (head + tail towers), BM=64, 192 CTAs, 2 CTA/SM
    {
        GJob jh = {}, jt = {};
        jh.aH = p_h1H;      jh.aL = p_h1L;      jh.lda = N1;
        jh.bH = p_w2hH;     jh.bL = p_w2hL;
        jh.bias = hb2;
        jh.outH = p_eHH; jh.outL = p_eHL; jh.outF = p_eH; jh.ldo = HH2;
        jh.relu = 1;
        jt.aH = p_h1H + HH; jt.aL = p_h1L + HH; jt.lda = N1;
        jt.bH = p_w2tH;     jt.bL = p_w2tL;
        jt.bias = tb2;
        jt.outF = p_eT; jt.ldo = HH2;
        jt.relu = 1;
        mma_gemm<64><<<dim3(6, ME / 64), 256, SMEM64>>>(jh, jt, 3, HH);
    }
    // 4) bilinear precompute, BM=64, 192 CTAs, 2 CTA/SM
    {
        GJob j = {};
        j.aH = p_eHH; j.aL = p_eHL; j.lda = HH2;
        j.bH = p_bilH; j.bL = p_bilL;
        j.outF = p_hb; j.ldo = 2 * HH2;
        j.relu = 0;
        mma_gemm<64><<<dim3(2 * HH2 / 128, ME / 64), 256, SMEM64>>>(j, j, 999, HH2);
    }

    // 5) per-entity linear terms
    lin_kernel<<<ME, 64>>>(lW);

    // 6) per-relation logits + loss partials
    rel_kernel<<<RELBLOCKS, 256>>>(rel_head, rel_tail, rel_label, lb, logits_out);

    // 7) loss
    if (off >= 1) loss_reduce_kernel<<<1, 256>>>((float*)d_out);
}

// round 13
// speedup vs baseline: 1.7423x; 1.0889x over previous
#include <cuda_runtime.h>
#include <cuda_bf16.h>
#include <stdint.h>
#include <math.h>

// ---------------- problem constants ----------------
#define BB   16
#define SS_  512
#define DD   768
#define EE   128
#define RR   2048
#define HH   768
#define HH2  384
#define ME   (BB * EE)        // 2048 entity rows
#define NREL (BB * RR)        // 32768 relations
#define RELBLOCKS (NREL / 8)
#define N1   (2 * HH)         // 1536 (head|tail fused layer1 output)

// ---------------- scratch (static device globals) ----------------
__device__ __nv_bfloat16 g_repH[ME * DD],  g_repL[ME * DD];
__device__ __nv_bfloat16 g_w1H [N1 * DD],  g_w1L [N1 * DD];
__device__ __nv_bfloat16 g_h1H [ME * N1],  g_h1L [ME * N1];
__device__ __nv_bfloat16 g_w2hH[HH2 * HH], g_w2hL[HH2 * HH];
__device__ __nv_bfloat16 g_w2tH[HH2 * HH], g_w2tL[HH2 * HH];
__device__ __nv_bfloat16 g_eHH [ME * HH2], g_eHL [ME * HH2];
__device__ __nv_bfloat16 g_bilH[2 * HH2 * HH2], g_bilL[2 * HH2 * HH2];
__device__ float g_embW1[3 * N1];
__device__ float g_eH[ME * HH2], g_eT[ME * HH2];
__device__ float g_hb[ME * 2 * HH2];
__device__ float g_hlin[ME * 2], g_tlin[ME * 2];
__device__ float g_partials[RELBLOCKS];

// ---------------- helpers ----------------
__device__ __forceinline__ uint32_t smem_u32(const void* p) {
    uint32_t a;
    asm("{ .reg .u64 t; cvta.to.shared.u64 t, %1; cvt.u32.u64 %0, t; }" : "=r"(a) : "l"(p));
    return a;
}
__device__ __forceinline__ void cpa16(uint32_t dst, const void* src) {
    asm volatile("cp.async.cg.shared.global [%0], [%1], 16;" :: "r"(dst), "l"(src));
}
#define CP_COMMIT() asm volatile("cp.async.commit_group;" ::: "memory")

#define LDSM4(r, addr) \
    asm volatile("ldmatrix.sync.aligned.m8n8.x4.shared.b16 {%0,%1,%2,%3}, [%4];" \
        : "=r"((r)[0]), "=r"((r)[1]), "=r"((r)[2]), "=r"((r)[3]) : "r"(addr))

#define MMA16816(d, a, b) \
    asm volatile("mma.sync.aligned.m16n8k16.row.col.f32.bf16.bf16.f32 " \
        "{%0,%1,%2,%3}, {%4,%5,%6,%7}, {%8,%9}, {%0,%1,%2,%3};" \
        : "+f"((d)[0]), "+f"((d)[1]), "+f"((d)[2]), "+f"((d)[3]) \
        : "r"((a)[0]), "r"((a)[1]), "r"((a)[2]), "r"((a)[3]), "r"((b)[0]), "r"((b)[1]))

__device__ __forceinline__ void split2(float x, __nv_bfloat16& h, __nv_bfloat16& l) {
    h = __float2bfloat16(x);
    l = __float2bfloat16(x - __bfloat162float(h));
}

// ---------------- gather + convert (hid part only) ----------------
__global__ void gather_kernel(const float* __restrict__ hs,
                              const int* __restrict__ es) {
    int m = blockIdx.x;
    int b = m >> 7;
    int s = es[m];
    const float* src = hs + ((size_t)b * SS_ + s) * DD;
    size_t rb = (size_t)m * DD;
    for (int i = threadIdx.x; i < DD; i += 256) {
        __nv_bfloat16 h, l;
        split2(src[i], h, l);
        g_repH[rb + i] = h; g_repL[rb + i] = l;
    }
}

// ---------------- embW1[l, n] = emb[l] @ W1_bottom[:, n] + b1[n]  (exact fp32) ----------------
__global__ void embw1_kernel(const float* __restrict__ emb,
                             const float* __restrict__ hW1, const float* __restrict__ hb1,
                             const float* __restrict__ tW1, const float* __restrict__ tb1) {
    int o = blockIdx.x * 8 + (threadIdx.x >> 5);
    int lane = threadIdx.x & 31;
    int l = o / N1, n = o % N1;
    const float* er = emb + (size_t)l * DD;
    const float* w;
    float bias;
    if (n < HH) { w = hW1 + (size_t)DD * HH + n;        bias = hb1[n]; }
    else        { w = tW1 + (size_t)DD * HH + (n - HH); bias = tb1[n - HH]; }
    float a = 0.f;
    for (int k = lane; k < DD; k += 32) a = fmaf(er[k], w[(size_t)k * HH], a);
#pragma unroll
    for (int off = 16; off; off >>= 1) a += __shfl_xor_sync(0xffffffffu, a, off);
    if (lane == 0) g_embW1[o] = a + bias;
}

// ---------------- all weight transposes+converts in ONE launch ----------------
__global__ void wconv_all(const float* __restrict__ hW1, const float* __restrict__ tW1,
                          const float* __restrict__ hW2, const float* __restrict__ tW2,
                          const float* __restrict__ bil) {
    __shared__ float t[32][33];
    int id = blockIdx.x;
    const float* W; int K, N; __nv_bfloat16 *oH, *oL;
    if (id < 576)       { W = hW1;             K = 768; N = 768; oH = g_w1H;             oL = g_w1L; }
    else if (id < 1152) { W = tW1;             K = 768; N = 768; oH = g_w1H + 768 * 768; oL = g_w1L + 768 * 768; id -= 576; }
    else if (id < 1440) { W = hW2;             K = 768; N = 384; oH = g_w2hH;            oL = g_w2hL; id -= 1152; }
    else if (id < 1728) { W = tW2;             K = 768; N = 384; oH = g_w2tH;            oL = g_w2tL; id -= 1440; }
    else if (id < 1872) { W = bil;             K = 384; N = 384; oH = g_bilH;            oL = g_bilL; id -= 1728; }
    else                { W = bil + 384 * 384; K = 384; N = 384; oH = g_bilH + 384 * 384; oL = g_bilL + 384 * 384; id -= 1872; }
    int ntiles = N / 32;
    int n0 = (id % ntiles) * 32, k0 = (id / ntiles) * 32;
    int tx = threadIdx.x, ty = threadIdx.y;
#pragma unroll
    for (int j = 0; j < 32; j += 8)
        t[ty + j][tx] = W[(size_t)(k0 + ty + j) * N + n0 + tx];
    __syncthreads();
#pragma unroll
    for (int j = 0; j < 32; j += 8) {
        int n = n0 + ty + j, k = k0 + tx;
        __nv_bfloat16 h, l;
        split2(t[tx][ty + j], h, l);
        oH[(size_t)n * K + k] = h;
        oL[(size_t)n * K + k] = l;
    }
}

// ---------------- mma.sync split-bf16 GEMM, 2-stage cp.async, tiled <BM,BN> ----------------
struct GJob {
    const __nv_bfloat16 *aH, *aL; int lda;
    const __nv_bfloat16 *bH, *bL;            // ldb = K
    const float* bias;
    const float* rowTab; const int* rowLab; int ldTab;
    __nv_bfloat16 *outH, *outL;
    float* outF;
    int ldo;
    int relu;
};

template <int BM, int BN>
__device__ __forceinline__ void load_stage(uint32_t sbase, const GJob& j,
                                           int m0, int n0, int k0, int tid, int K) {
    const int ACH = BM * 4;                  // 16B chunks per A matrix
    const int BCH = BN * 4;                  // 16B chunks per B matrix
#pragma unroll
    for (int idx = tid; idx < 2 * ACH + 2 * BCH; idx += 256) {
        if (idx < ACH) {
            int row = idx >> 2, ch = idx & 3;
            cpa16(sbase + row * 80 + ch * 16, j.aH + (size_t)(m0 + row) * j.lda + k0 + ch * 8);
        } else if (idx < 2 * ACH) {
            int q = idx - ACH; int row = q >> 2, ch = q & 3;
            cpa16(sbase + BM * 80 + row * 80 + ch * 16, j.aL + (size_t)(m0 + row) * j.lda + k0 + ch * 8);
        } else if (idx < 2 * ACH + BCH) {
            int q = idx - 2 * ACH; int row = q >> 2, ch = q & 3;
            cpa16(sbase + 2 * BM * 80 + row * 80 + ch * 16, j.bH + (size_t)(n0 + row) * K + k0 + ch * 8);
        } else {
            int q = idx - 2 * ACH - BCH; int row = q >> 2, ch = q & 3;
            cpa16(sbase + 2 * BM * 80 + BN * 80 + row * 80 + ch * 16, j.bL + (size_t)(n0 + row) * K + k0 + ch * 8);
        }
    }
}

template <int BM, int BN, int MINB>
__global__ void __launch_bounds__(256, MINB)
mma_gemm(GJob j0, GJob j1, int splitX, int K) {
    constexpr int MT = BM / 32;              // m16 tiles per warp
    constexpr int NT = BN / 32;              // n8 tiles per warp
    constexpr int NP = BN / 64;              // B ldmatrix pairs per warp
    constexpr int MAT_A = BM * 80;
    constexpr int MAT_B = BN * 80;
    constexpr int OFF_B = 2 * BM * 80;
    constexpr int STAGE = 2 * BM * 80 + 2 * BN * 80;
    extern __shared__ char smem[];
    const uint32_t sb = smem_u32(smem);
    const int tid = threadIdx.x;
    const int wid = tid >> 5, lane = tid & 31;

    const int isJ1 = (blockIdx.x >= splitX);
    const GJob j = isJ1 ? j1 : j0;
    const int nx = blockIdx.x - (isJ1 ? splitX : 0);
    const int m0 = blockIdx.y * BM, n0 = nx * BN;
    const int warpM = (wid >> 2) * (BM / 2);
    const int warpN = (wid & 3) * (BN / 4);

    const uint32_t aOff = (warpM + (lane & 15)) * 80 + (lane >> 4) * 16;
    const uint32_t bOff = (warpN + (lane & 7) + ((lane >> 4) & 1) * 8) * 80
                        + ((lane >> 3) & 1) * 16;

    float acc[MT][NT][4];
#pragma unroll
    for (int i = 0; i < MT; i++)
#pragma unroll
        for (int jt = 0; jt < NT; jt++)
#pragma unroll
            for (int q = 0; q < 4; q++) acc[i][jt][q] = 0.f;

    const int NC = K >> 5;

    load_stage<BM, BN>(sb, j, m0, n0, 0, tid, K);
    CP_COMMIT();

    for (int c = 0; c < NC; c++) {
        asm volatile("cp.async.wait_group 0;" ::: "memory");
        __syncthreads();

        if (c + 1 < NC) {
            load_stage<BM, BN>(sb + ((c + 1) & 1) * STAGE, j, m0, n0, (c + 1) * 32, tid, K);
            CP_COMMIT();
        }

        const uint32_t st = sb + (c & 1) * STAGE;
#pragma unroll
        for (int ks = 0; ks < 2; ks++) {
            uint32_t bh[NP][4], bl[NP][4];
#pragma unroll
            for (int np = 0; np < NP; np++) {
                uint32_t bd = st + OFF_B + bOff + np * (16 * 80) + ks * 32;
                LDSM4(bh[np], bd);
                LDSM4(bl[np], bd + MAT_B);
            }
            // per-mt A fragments; 3 nt-passes of independent accumulator chains
#pragma unroll
            for (int mt = 0; mt < MT; mt++) {
                uint32_t ah[4], al[4];
                uint32_t ad = st + aOff + mt * (16 * 80) + ks * 32;
                LDSM4(ah, ad);
                LDSM4(al, ad + MAT_A);
#pragma unroll
                for (int nt = 0; nt < NT; nt++)
                    MMA16816(acc[mt][nt], ah, (&bh[nt >> 1][(nt & 1) * 2]));
#pragma unroll
                for (int nt = 0; nt < NT; nt++)
                    MMA16816(acc[mt][nt], ah, (&bl[nt >> 1][(nt & 1) * 2]));
#pragma unroll
                for (int nt = 0; nt < NT; nt++)
                    MMA16816(acc[mt][nt], al, (&bh[nt >> 1][(nt & 1) * 2]));
            }
        }
        __syncthreads();
    }

    // ---------------- epilogue ----------------
    const int lr = lane >> 2;
    const int lc = (lane & 3) * 2;
#pragma unroll
    for (int mt = 0; mt < MT; mt++) {
        int grow = m0 + warpM + mt * 16 + lr;
        int lab0 = 0, lab1 = 0;
        if (j.rowTab) { lab0 = j.rowLab[grow]; lab1 = j.rowLab[grow + 8]; }
#pragma unroll
        for (int nt = 0; nt < NT; nt++) {
            int gcol = n0 + warpN + nt * 8 + lc;
            float v0 = acc[mt][nt][0], v1 = acc[mt][nt][1];
            float v2 = acc[mt][nt][2], v3 = acc[mt][nt][3];
            if (j.bias) {
                float b0v = __ldg(j.bias + gcol), b1v = __ldg(j.bias + gcol + 1);
                v0 += b0v; v1 += b1v; v2 += b0v; v3 += b1v;
            }
            if (j.rowTab) {
                v0 += __ldg(j.rowTab + (size_t)lab0 * j.ldTab + gcol);
                v1 += __ldg(j.rowTab + (size_t)lab0 * j.ldTab + gcol + 1);
                v2 += __ldg(j.rowTab + (size_t)lab1 * j.ldTab + gcol);
                v3 += __ldg(j.rowTab + (size_t)lab1 * j.ldTab + gcol + 1);
            }
            if (j.relu) {
                v0 = fmaxf(v0, 0.f); v1 = fmaxf(v1, 0.f);
                v2 = fmaxf(v2, 0.f); v3 = fmaxf(v3, 0.f);
            }
            if (j.outF) {
                *(float2*)(j.outF + (size_t)grow * j.ldo + gcol)       = make_float2(v0, v1);
                *(float2*)(j.outF + (size_t)(grow + 8) * j.ldo + gcol) = make_float2(v2, v3);
            }
            if (j.outH) {
                __nv_bfloat16 h0, l0, h1, l1, h2, l2, h3, l3;
                split2(v0, h0, l0); split2(v1, h1, l1);
                split2(v2, h2, l2); split2(v3, h3, l3);
                *(__nv_bfloat162*)(j.outH + (size_t)grow * j.ldo + gcol)       = __nv_bfloat162(h0, h1);
                *(__nv_bfloat162*)(j.outL + (size_t)grow * j.ldo + gcol)       = __nv_bfloat162(l0, l1);
                *(__nv_bfloat162*)(j.outH + (size_t)(grow + 8) * j.ldo + gcol) = __nv_bfloat162(h2, h3);
                *(__nv_bfloat162*)(j.outL + (size_t)(grow + 8) * j.ldo + gcol) = __nv_bfloat162(l2, l3);
            }
        }
    }
}

// ---------------- per-entity linear terms ----------------
__global__ void lin_kernel(const float* __restrict__ lW) {
    int m = blockIdx.x;
    int warp = threadIdx.x >> 5;
    int lane = threadIdx.x & 31;
    const float* src = (warp == 0) ? (g_eH + (size_t)m * HH2) : (g_eT + (size_t)m * HH2);
    int wbase = warp * HH2;
    float a0 = 0.f, a1 = 0.f;
    for (int i = lane; i < HH2; i += 32) {
        float x = src[i];
        a0 = fmaf(x, lW[(wbase + i) * 2 + 0], a0);
        a1 = fmaf(x, lW[(wbase + i) * 2 + 1], a1);
    }
#pragma unroll
    for (int off = 16; off; off >>= 1) {
        a0 += __shfl_xor_sync(0xffffffffu, a0, off);
        a1 += __shfl_xor_sync(0xffffffffu, a1, off);
    }
    if (lane == 0) {
        float* dst = (warp == 0) ? g_hlin : g_tlin;
        dst[m * 2 + 0] = a0;
        dst[m * 2 + 1] = a1;
    }
}

// ---------------- per-relation logits + NLL partials (float4-vectorized) ----------------
__global__ void rel_kernel(const int* __restrict__ rel_head, const int* __restrict__ rel_tail,
                           const int* __restrict__ rel_label, const float* __restrict__ lb,
                           float* __restrict__ out_logits) {
    int warp = threadIdx.x >> 5;
    int lane = threadIdx.x & 31;
    int r = blockIdx.x * 8 + warp;
    int b = r / RR;
    int hidx = rel_head[r];
    int tidx = rel_tail[r];
    size_t hm = (size_t)(b * EE + hidx);
    size_t tm = (size_t)(b * EE + tidx);
    const float4* hb4 = (const float4*)(g_hb + hm * (2 * HH2));
    const float4* t4  = (const float4*)(g_eT + tm * HH2);
    float a0 = 0.f, a1 = 0.f;
#pragma unroll
    for (int i = 0; i < 3; i++) {
        int jx = i * 32 + lane;
        float4 t = t4[jx];
        float4 h0 = hb4[jx];
        float4 h1 = hb4[96 + jx];
        a0 = fmaf(h0.x, t.x, a0); a0 = fmaf(h0.y, t.y, a0);
        a0 = fmaf(h0.z, t.z, a0); a0 = fmaf(h0.w, t.w, a0);
        a1 = fmaf(h1.x, t.x, a1); a1 = fmaf(h1.y, t.y, a1);
        a1 = fmaf(h1.z, t.z, a1); a1 = fmaf(h1.w, t.w, a1);
    }
#pragma unroll
    for (int off = 16; off; off >>= 1) {
        a0 += __shfl_xor_sync(0xffffffffu, a0, off);
        a1 += __shfl_xor_sync(0xffffffffu, a1, off);
    }
    __shared__ float sloss[8];
    if (lane == 0) {
        float l0 = a0 + g_hlin[hm * 2 + 0] + g_tlin[tm * 2 + 0] + lb[0];
        float l1 = a1 + g_hlin[hm * 2 + 1] + g_tlin[tm * 2 + 1] + lb[1];
        out_logits[(size_t)r * 2 + 0] = l0;
        out_logits[(size_t)r * 2 + 1] = l1;
        float mx = fmaxf(l0, l1);
        float lse = mx + logf(expf(l0 - mx) + expf(l1 - mx));
        int lab = rel_label[r];
        sloss[warp] = (lab ? l1 : l0) - lse;
    }
    __syncthreads();
    if (threadIdx.x == 0) {
        float s = 0.f;
#pragma unroll
        for (int i = 0; i < 8; i++) s += sloss[i];
        g_partials[blockIdx.x] = s;
    }
}

__global__ void loss_reduce_kernel(float* __restrict__ out_loss) {
    __shared__ float sh[256];
    float s = 0.f;
    for (int i = threadIdx.x; i < RELBLOCKS; i += 256) s += g_partials[i];
    sh[threadIdx.x] = s;
    __syncthreads();
    for (int off = 128; off; off >>= 1) {
        if (threadIdx.x < off) sh[threadIdx.x] += sh[threadIdx.x + off];
        __syncthreads();
    }
    if (threadIdx.x == 0) *out_loss = -sh[0] / (float)NREL;
}

// ---------------- host launch ----------------
#define SMEM_64_128 (2 * (2 * 64 * 80 + 2 * 128 * 80))   // 61440
#define SMEM_64_64  (2 * (2 * 64 * 80 + 2 * 64 * 80))    // 40960

extern "C" void kernel_launch(void* const* d_in, const int* in_sizes, int n_in,
                              void* d_out, int out_size) {
    const float* hs        = (const float*)d_in[0];
    const float* emb       = (const float*)d_in[1];
    const float* hW1       = (const float*)d_in[2];
    const float* hb1       = (const float*)d_in[3];
    const float* hW2       = (const float*)d_in[4];
    const float* hb2       = (const float*)d_in[5];
    const float* tW1       = (const float*)d_in[6];
    const float* tb1       = (const float*)d_in[7];
    const float* tW2       = (const float*)d_in[8];
    const float* tb2       = (const float*)d_in[9];
    const float* bil_w     = (const float*)d_in[10];
    const float* lW        = (const float*)d_in[11];
    const float* lb        = (const float*)d_in[12];
    const int*   ent_start = (const int*)d_in[13];
    const int*   ent_label = (const int*)d_in[14];
    const int*   rel_head  = (const int*)d_in[15];
    const int*   rel_tail  = (const int*)d_in[16];
    const int*   rel_label = (const int*)d_in[17];

    cudaFuncSetAttribute(mma_gemm<64, 128, 2>, cudaFuncAttributeMaxDynamicSharedMemorySize, SMEM_64_128);
    cudaFuncSetAttribute(mma_gemm<64, 64, 3>,  cudaFuncAttributeMaxDynamicSharedMemorySize, SMEM_64_64);

    __nv_bfloat16 *p_repH, *p_repL, *p_w1H, *p_w1L, *p_h1H, *p_h1L;
    __nv_bfloat16 *p_w2hH, *p_w2hL, *p_w2tH, *p_w2tL, *p_eHH, *p_eHL, *p_bilH, *p_bilL;
    float *p_eH, *p_eT, *p_hb, *p_embW1;
    cudaGetSymbolAddress((void**)&p_repH, g_repH); cudaGetSymbolAddress((void**)&p_repL, g_repL);
    cudaGetSymbolAddress((void**)&p_w1H,  g_w1H ); cudaGetSymbolAddress((void**)&p_w1L,  g_w1L );
    cudaGetSymbolAddress((void**)&p_h1H,  g_h1H ); cudaGetSymbolAddress((void**)&p_h1L,  g_h1L );
    cudaGetSymbolAddress((void**)&p_w2hH, g_w2hH); cudaGetSymbolAddress((void**)&p_w2hL, g_w2hL);
    cudaGetSymbolAddress((void**)&p_w2tH, g_w2tH); cudaGetSymbolAddress((void**)&p_w2tL, g_w2tL);
    cudaGetSymbolAddress((void**)&p_eHH,  g_eHH ); cudaGetSymbolAddress((void**)&p_eHL,  g_eHL );
    cudaGetSymbolAddress((void**)&p_bilH, g_bilH); cudaGetSymbolAddress((void**)&p_bilL, g_bilL);
    cudaGetSymbolAddress((void**)&p_eH,   g_eH  ); cudaGetSymbolAddress((void**)&p_eT,   g_eT  );
    cudaGetSymbolAddress((void**)&p_hb,   g_hb  ); cudaGetSymbolAddress((void**)&p_embW1, g_embW1);

    const int logit_elems = NREL * 2;
    int off = out_size - logit_elems;
    if (off < 0) off = 0;
    float* logits_out = (float*)d_out + off;

    // 1) independent prep
    gather_kernel<<<ME, 256>>>(hs, ent_start);
    embw1_kernel<<<576, 256>>>(emb, hW1, hb1, tW1, tb1);
    wconv_all<<<2016, dim3(32, 8)>>>(hW1, tW1, hW2, tW2, bil_w);

    // 2) layer 1 (fused head|tail): [2048,768] x [1536,768]^T + embW1[label], relu
    //    BM=64, BN=128 -> grid (12, 32) = 384 CTAs, 2 CTAs/SM
    {
        GJob j = {};
        j.aH = p_repH; j.aL = p_repL; j.lda = DD;
        j.bH = p_w1H;  j.bL = p_w1L;
        j.rowTab = p_embW1; j.rowLab = ent_label; j.ldTab = N1;
        j.outH = p_h1H; j.outL = p_h1L; j.ldo = N1;
        j.relu = 1;
        mma_gemm<64, 128, 2><<<dim3(N1 / 128, ME / 64), 256, SMEM_64_128>>>(j, j, 999, DD);
    }
    // 3) layer 2 merged (head + tail towers), BM=64 BN=64 -> grid (12, 32) = 384 CTAs, 3 CTAs/SM
    {
        GJob jh = {}, jt = {};
        jh.aH = p_h1H;      jh.aL = p_h1L;      jh.lda = N1;
        jh.bH = p_w2hH;     jh.bL = p_w2hL;
        jh.bias = hb2;
        jh.outH = p_eHH; jh.outL = p_eHL; jh.outF = p_eH; jh.ldo = HH2;
        jh.relu = 1;
        jt.aH = p_h1H + HH; jt.aL = p_h1L + HH; jt.lda = N1;
        jt.bH = p_w2tH;     jt.bL = p_w2tL;
        jt.bias = tb2;
        jt.outF = p_eT; jt.ldo = HH2;
        jt.relu = 1;
        mma_gemm<64, 64, 3><<<dim3(12, ME / 64), 256, SMEM_64_64>>>(jh, jt, 6, HH);
    }
    // 4) bilinear precompute, BM=64 BN=64 -> grid (12, 32) = 384 CTAs, 3 CTAs/SM
    {
        GJob j = {};
        j.aH = p_eHH; j.aL = p_eHL; j.lda = HH2;
        j.bH = p_bilH; j.bL = p_bilL;
        j.outF = p_hb; j.ldo = 2 * HH2;
        j.relu = 0;
        mma_gemm<64, 64, 3><<<dim3(12, ME / 64), 256, SMEM_64_64>>>(j, j, 999, HH2);
    }

    // 5) per-entity linear terms
    lin_kernel<<<ME, 64>>>(lW);

    // 6) per-relation logits + loss partials
    rel_kernel<<<RELBLOCKS, 256>>>(rel_head, rel_tail, rel_label, lb, logits_out);

    // 7) loss
    if (off >= 1) loss_reduce_kernel<<<1, 256>>>((float*)d_out);
}